// round 13
// baseline (speedup 1.0000x reference)
#include <cuda_runtime.h>
#include <cuda_fp16.h>
#include <math.h>
#include <stdint.h>

#define TT 4096
#define DD 2048
#define FFDIM 8192
#define EE 8

// ---------------- device scratch (static: no allocations allowed) ----------------
static __device__ __half g_h[(size_t)TT * FFDIM];   // gelu(x@W1) half, permuted rows (64MB)
static __device__ __half g_xh[(size_t)TT * DD];     // x converted to half (16MB)
static __device__ float  g_w[TT];
static __device__ int    g_idx[TT];
static __device__ int    g_perm[TT];
static __device__ int    g_counts[EE];
static __device__ int    g_offs[EE + 1];
static __device__ int    g_cursor[EE];

// ---------------- helpers ----------------
__device__ __forceinline__ float gelu_exact(float v) {
    return 0.5f * v * (1.0f + erff(v * 0.70710678118654752440f));
}
// m16n8k16 fp16 MMA, fp32 accumulate (sm_80+ PTX, no arch-suffix gating)
__device__ __forceinline__ void mma16(float& d0, float& d1, float& d2, float& d3,
                                      uint32_t a0, uint32_t a1, uint32_t a2, uint32_t a3,
                                      uint32_t b0, uint32_t b1) {
    asm volatile(
        "mma.sync.aligned.m16n8k16.row.col.f32.f16.f16.f32 "
        "{%0,%1,%2,%3}, {%4,%5,%6,%7}, {%8,%9}, {%0,%1,%2,%3};"
        : "+f"(d0), "+f"(d1), "+f"(d2), "+f"(d3)
        : "r"(a0), "r"(a1), "r"(a2), "r"(a3), "r"(b0), "r"(b1));
}
__device__ __forceinline__ uint32_t h2pack(float lo, float hi) {
    __half2 h = __floats2half2_rn(lo, hi);
    return *(uint32_t*)&h;
}

// ---------------- routing kernels ----------------
__global__ void k_init() {
    int i = threadIdx.x;
    if (i < EE) g_counts[i] = 0;
}

__global__ void k_router(const float* __restrict__ x, const float* __restrict__ Wr) {
    int warp = (blockIdx.x * blockDim.x + threadIdx.x) >> 5;
    int lane = threadIdx.x & 31;
    if (warp >= TT) return;
    const float* xr = x + (size_t)warp * DD;
    float acc[EE];
#pragma unroll
    for (int e = 0; e < EE; e++) acc[e] = 0.f;
    for (int i = lane; i < DD; i += 32) {
        float xv = xr[i];
#pragma unroll
        for (int e = 0; e < EE; e++) acc[e] = fmaf(xv, Wr[e * DD + i], acc[e]);
    }
#pragma unroll
    for (int e = 0; e < EE; e++) {
#pragma unroll
        for (int off = 16; off > 0; off >>= 1)
            acc[e] += __shfl_xor_sync(0xffffffffu, acc[e], off);
    }
    if (lane == 0) {
        int best = 0;
        float bm = acc[0];
#pragma unroll
        for (int e = 1; e < EE; e++)
            if (acc[e] > bm) { bm = acc[e]; best = e; }  // strict > : first-max = argmax
        float s = 0.f;
#pragma unroll
        for (int e = 0; e < EE; e++) s += expf(acc[e] - bm);
        g_idx[warp] = best;
        g_w[warp] = 1.f / s;  // max softmax prob
        atomicAdd(&g_counts[best], 1);
    }
}

__global__ void k_scan() {
    if (threadIdx.x == 0) {
        int s = 0;
#pragma unroll
        for (int e = 0; e < EE; e++) {
            g_offs[e] = s;
            g_cursor[e] = s;
            s += g_counts[e];
        }
        g_offs[EE] = s;
    }
}

__global__ void k_scatter() {
    int t = blockIdx.x * blockDim.x + threadIdx.x;
    if (t < TT) {
        int pos = atomicAdd(&g_cursor[g_idx[t]], 1);
        g_perm[pos] = t;
    }
}

// convert x fp32 -> half once per launch (8 elements/thread)
__global__ void k_convx(const float4* __restrict__ x, uint4* __restrict__ xh) {
    size_t i = (size_t)blockIdx.x * blockDim.x + threadIdx.x;  // TT*DD/8 threads
    float4 a = x[2 * i];
    float4 b = x[2 * i + 1];
    uint4 o;
    o.x = h2pack(a.x, a.y);
    o.y = h2pack(a.z, a.w);
    o.z = h2pack(b.x, b.y);
    o.w = h2pack(b.z, b.w);
    xh[i] = o;
}

// ---------------- fp16 mma.sync grouped GEMM ----------------
// CTA 128x128, K-chunk 32, 8 warps (2m x 4n), warp tile 64x32, m16n8k16 fp32-acc.
// A (half) staged directly; B (fp32 weights) converted at staging.
// Bs2 layout: [k/2][n] half2 (k-pair interleave) so B fragments are LDS.32.
// MODE 1: g_h[segRow, n] = half( gelu( sum_k xh[perm[row], k] * W1[e, k, n] ) )
// MODE 2: out[tok, n]    = w[tok] * sum_k g_h[segRow, k] * W2[e, k, n]
#define SA4 20   // As row stride in half2 units (frag banks 20g+tg: all-distinct)
#define SB4 136  // Bs2 row stride in half2 units (136 mod 32 = 8 -> frag banks 8tg+g)

template <int KDIM, int NDIM, int MODE>
__global__ void __launch_bounds__(256) k_gemm(const float* __restrict__ B,
                                              float* __restrict__ C) {
    __shared__ int toks[128];
    __shared__ float wts[128];
    __shared__ uint32_t smA[2][128 * SA4];  // [buf][row*20 + kpair]  (half2)
    __shared__ uint32_t smB[2][16 * SB4];   // [buf][kpair*136 + n]   (half2)

    const int e = blockIdx.z;
    const int segOff = g_offs[e];
    const int cnt = g_offs[e + 1] - segOff;
    const int rowBase = blockIdx.y * 128;
    if (rowBase >= cnt) return;  // padded grid: empty tiles exit immediately
    const int colBase = blockIdx.x * 128;
    const int tid = threadIdx.x;

    {
        int r = rowBase + (tid & 127);
        int tk = (r < cnt) ? g_perm[segOff + r] : -1;
        if (tid < 128) {
            toks[tid] = tk;
            wts[tid] = (tk >= 0) ? g_w[tk] : 0.f;
        }
    }
    __syncthreads();

    // ---- staging mappings ----
    // A (half): thread -> row = tid>>1, k-halves [kseg*16, kseg*16+16)
    const int rowA = tid >> 1;
    const int kseg = tid & 1;
    const __half* Aeff = (MODE == 1) ? g_xh : g_h;
    const __half* aSrc;
    {
        int ar;
        if (MODE == 1) {
            int tk = toks[rowA];
            ar = (tk >= 0) ? tk : 0;
        } else {
            ar = segOff + ((rowBase + rowA < cnt) ? rowBase + rowA : 0);
        }
        aSrc = Aeff + (size_t)ar * KDIM + kseg * 16;
    }
    // B (fp32): thread -> k-pair kp = tid>>4, n0 = (tid&15)*8  (8 n-columns)
    const int kp = tid >> 4;
    const int n0 = (tid & 15) * 8;
    const float* bP = B + ((size_t)e * KDIM + 2 * kp) * NDIM + colBase + n0;

    // register prefetch stages (2 chunks ahead)
    uint4 pa[2][2];
    float4 pb[2][4];

    auto ldg_stage = [&](int st, int c) {
        const __half* a = aSrc + (size_t)c * 32;
        pa[st][0] = *(const uint4*)a;
        pa[st][1] = *(const uint4*)(a + 8);
        const float* b = bP + (size_t)c * 32 * NDIM;
        pb[st][0] = *(const float4*)b;
        pb[st][1] = *(const float4*)(b + NDIM);
        pb[st][2] = *(const float4*)(b + 4);
        pb[st][3] = *(const float4*)(b + NDIM + 4);
    };
    auto sts_stage = [&](int buf, int st) {
        // A: two STS.128 (16 halves) at [rowA][kseg*8 .. +8)
        uint32_t* da = &smA[buf][rowA * SA4 + kseg * 8];
        *(uint4*)da = pa[st][0];
        *(uint4*)(da + 4) = pa[st][1];
        // B: interleave k-pairs -> half2, two STS.128 at [kp][n0], [kp][n0+4]
        uint32_t* db = &smB[buf][kp * SB4 + n0];
        uint4 v0, v1;
        v0.x = h2pack(pb[st][0].x, pb[st][1].x);
        v0.y = h2pack(pb[st][0].y, pb[st][1].y);
        v0.z = h2pack(pb[st][0].z, pb[st][1].z);
        v0.w = h2pack(pb[st][0].w, pb[st][1].w);
        v1.x = h2pack(pb[st][2].x, pb[st][3].x);
        v1.y = h2pack(pb[st][2].y, pb[st][3].y);
        v1.z = h2pack(pb[st][2].z, pb[st][3].z);
        v1.w = h2pack(pb[st][2].w, pb[st][3].w);
        *(uint4*)db = v0;
        *(uint4*)(db + 4) = v1;
    };

    // ---- fragment mapping: 8 warps, 2m x 4n, warp tile 64x32 ----
    const int w = tid >> 5;
    const int lane = tid & 31;
    const int g = lane >> 2;
    const int tg = lane & 3;
    const int wm = (w & 1) * 64;
    const int wn = (w >> 1) * 32;

    float acc[4][4][4];
#pragma unroll
    for (int i = 0; i < 4; i++)
#pragma unroll
        for (int j = 0; j < 4; j++)
#pragma unroll
            for (int q = 0; q < 4; q++) acc[i][j][q] = 0.f;

    const int NC = KDIM / 32;
    ldg_stage(0, 0);
    ldg_stage(1, 1);
    sts_stage(0, 0);
    __syncthreads();

    for (int it = 0; it < NC; ++it) {
        const int buf = it & 1;
        // issue LDG for chunk it+2 into the stage freed last iteration
        if (it + 2 < NC) ldg_stage(it & 1, it + 2);

        const uint32_t* As = smA[buf];
        const uint32_t* Bs = smB[buf];
#pragma unroll
        for (int s = 0; s < 2; s++) {
            const int kc = s * 8;  // half2 k-offset
            uint32_t ua[4][4], ub[4][2];
#pragma unroll
            for (int i = 0; i < 4; i++) {
                const int row = wm + i * 16 + g;
                ua[i][0] = As[row * SA4 + kc + tg];
                ua[i][1] = As[(row + 8) * SA4 + kc + tg];
                ua[i][2] = As[row * SA4 + kc + tg + 4];
                ua[i][3] = As[(row + 8) * SA4 + kc + tg + 4];
            }
#pragma unroll
            for (int j = 0; j < 4; j++) {
                const int n = wn + j * 8 + g;
                ub[j][0] = Bs[(kc + tg) * SB4 + n];
                ub[j][1] = Bs[(kc + tg + 4) * SB4 + n];
            }
#pragma unroll
            for (int i = 0; i < 4; i++)
#pragma unroll
                for (int j = 0; j < 4; j++)
                    mma16(acc[i][j][0], acc[i][j][1], acc[i][j][2], acc[i][j][3],
                          ua[i][0], ua[i][1], ua[i][2], ua[i][3], ub[j][0], ub[j][1]);
        }

        // stage chunk it+1 into the other buffer (safe: all warps past buf^1 reads)
        if (it + 1 < NC) sts_stage(buf ^ 1, (it + 1) & 1);
        __syncthreads();
    }

    // ---- epilogue ----
#pragma unroll
    for (int i = 0; i < 4; i++) {
#pragma unroll
        for (int h = 0; h < 2; h++) {
            const int rl = wm + i * 16 + g + 8 * h;
            const int rg = rowBase + rl;
            if (rg >= cnt) continue;
            if (MODE == 1) {
                __half* out = g_h + (size_t)(segOff + rg) * NDIM + colBase;
#pragma unroll
                for (int j = 0; j < 4; j++) {
                    const int col = wn + j * 8 + 2 * tg;
                    __half2 v = __floats2half2_rn(gelu_exact(acc[i][j][2 * h]),
                                                  gelu_exact(acc[i][j][2 * h + 1]));
                    *(__half2*)(out + col) = v;
                }
            } else {
                float* out = C + (size_t)toks[rl] * NDIM + colBase;
                const float wv = wts[rl];
#pragma unroll
                for (int j = 0; j < 4; j++) {
                    const int col = wn + j * 8 + 2 * tg;
                    float2 v;
                    v.x = acc[i][j][2 * h] * wv;
                    v.y = acc[i][j][2 * h + 1] * wv;
                    *(float2*)(out + col) = v;
                }
            }
        }
    }
}

extern "C" void kernel_launch(void* const* d_in, const int* in_sizes, int n_in,
                              void* d_out, int out_size) {
    (void)in_sizes;
    (void)n_in;
    (void)out_size;
    const float* x  = (const float*)d_in[0];
    const float* Wr = (const float*)d_in[1];
    const float* W1 = (const float*)d_in[2];
    const float* W2 = (const float*)d_in[3];
    float* out = (float*)d_out;

    k_init<<<1, 32>>>();
    k_router<<<TT / 8, 256>>>(x, Wr);
    k_scan<<<1, 32>>>();
    k_scatter<<<TT / 256, 256>>>();

    __half* xh;
    cudaGetSymbolAddress((void**)&xh, g_xh);
    k_convx<<<(TT * DD / 8) / 256, 256>>>((const float4*)x, (uint4*)xh);

    dim3 g1(FFDIM / 128, TT / 128, EE);  // 64 x 32 x 8 (empty padded tiles exit)
    k_gemm<DD, FFDIM, 1><<<g1, 256>>>(W1, nullptr);

    dim3 g2(DD / 128, TT / 128, EE);     // 16 x 32 x 8
    k_gemm<FFDIM, DD, 2><<<g2, 256>>>(W2, out);
}

// round 17
// speedup vs baseline: 1.4485x; 1.4485x over previous
#include <cuda_runtime.h>
#include <cuda_fp16.h>
#include <math.h>
#include <stdint.h>

#define TT 4096
#define DD 2048
#define FFDIM 8192
#define EE 8

// ---------------- device scratch (static: no allocations allowed) ----------------
static __device__ __half    g_h[(size_t)TT * FFDIM];            // gelu(x@W1) half, permuted (64MB)
static __device__ __half    g_xh[(size_t)TT * DD];              // x as half (16MB)
static __device__ uint32_t  g_w1h[(size_t)EE * (DD / 2) * FFDIM];   // W1 half2 k-pair interleaved (256MB)
static __device__ uint32_t  g_w2h[(size_t)EE * (FFDIM / 2) * DD];   // W2 half2 k-pair interleaved (256MB)
static __device__ float     g_w[TT];
static __device__ int       g_idx[TT];
static __device__ int       g_perm[TT];
static __device__ int       g_counts[EE];
static __device__ int       g_offs[EE + 1];
static __device__ int       g_cursor[EE];

// ---------------- helpers ----------------
__device__ __forceinline__ float gelu_exact(float v) {
    return 0.5f * v * (1.0f + erff(v * 0.70710678118654752440f));
}
__device__ __forceinline__ void mma16(float& d0, float& d1, float& d2, float& d3,
                                      uint32_t a0, uint32_t a1, uint32_t a2, uint32_t a3,
                                      uint32_t b0, uint32_t b1) {
    asm volatile(
        "mma.sync.aligned.m16n8k16.row.col.f32.f16.f16.f32 "
        "{%0,%1,%2,%3}, {%4,%5,%6,%7}, {%8,%9}, {%0,%1,%2,%3};"
        : "+f"(d0), "+f"(d1), "+f"(d2), "+f"(d3)
        : "r"(a0), "r"(a1), "r"(a2), "r"(a3), "r"(b0), "r"(b1));
}
__device__ __forceinline__ uint32_t h2pack(float lo, float hi) {
    __half2 h = __floats2half2_rn(lo, hi);
    return *(uint32_t*)&h;
}
__device__ __forceinline__ uint32_t smem_u32(const void* p) {
    uint32_t a;
    asm("{ .reg .u64 t; cvta.to.shared.u64 t, %1; cvt.u32.u64 %0, t; }" : "=r"(a) : "l"(p));
    return a;
}
#define CPA16(dst, src) \
    asm volatile("cp.async.cg.shared.global [%0], [%1], 16;" :: "r"(dst), "l"(src))
#define CPA_COMMIT() asm volatile("cp.async.commit_group;" ::: "memory")
#define CPA_WAIT1() asm volatile("cp.async.wait_group 1;" ::: "memory")
#define CPA_WAIT0() asm volatile("cp.async.wait_group 0;" ::: "memory")

// SMEM: toks/wts @0..1024; 3 stages of [A: 128 rows x 20 half2 (80B/row), B: 16 kpairs x 136 half2 (544B/row)]
#define SA4 20
#define SB4 136
#define ASZ (128 * SA4 * 4)   // 10240
#define BSZ (16 * SB4 * 4)    // 8704
#define STAGE (ASZ + BSZ)     // 18944
#define OFF_STG 1024
#define SMEM_SZ (OFF_STG + 3 * STAGE)  // 57856 -> 2 CTAs/SM

// ---------------- routing kernels ----------------
__global__ void k_init() {
    int i = threadIdx.x;
    if (i < EE) g_counts[i] = 0;
}

__global__ void k_router(const float* __restrict__ x, const float* __restrict__ Wr) {
    int warp = (blockIdx.x * blockDim.x + threadIdx.x) >> 5;
    int lane = threadIdx.x & 31;
    if (warp >= TT) return;
    const float* xr = x + (size_t)warp * DD;
    float acc[EE];
#pragma unroll
    for (int e = 0; e < EE; e++) acc[e] = 0.f;
    for (int i = lane; i < DD; i += 32) {
        float xv = xr[i];
#pragma unroll
        for (int e = 0; e < EE; e++) acc[e] = fmaf(xv, Wr[e * DD + i], acc[e]);
    }
#pragma unroll
    for (int e = 0; e < EE; e++) {
#pragma unroll
        for (int off = 16; off > 0; off >>= 1)
            acc[e] += __shfl_xor_sync(0xffffffffu, acc[e], off);
    }
    if (lane == 0) {
        int best = 0;
        float bm = acc[0];
#pragma unroll
        for (int e = 1; e < EE; e++)
            if (acc[e] > bm) { bm = acc[e]; best = e; }  // strict > : first-max = argmax
        float s = 0.f;
#pragma unroll
        for (int e = 0; e < EE; e++) s += expf(acc[e] - bm);
        g_idx[warp] = best;
        g_w[warp] = 1.f / s;  // max softmax prob
        atomicAdd(&g_counts[best], 1);
    }
}

__global__ void k_scan() {
    if (threadIdx.x == 0) {
        int s = 0;
#pragma unroll
        for (int e = 0; e < EE; e++) {
            g_offs[e] = s;
            g_cursor[e] = s;
            s += g_counts[e];
        }
        g_offs[EE] = s;
    }
}

__global__ void k_scatter() {
    int t = blockIdx.x * blockDim.x + threadIdx.x;
    if (t < TT) {
        int pos = atomicAdd(&g_cursor[g_idx[t]], 1);
        g_perm[pos] = t;
    }
}

// x fp32 -> half (8 elems/thread)
__global__ void k_convx(const float4* __restrict__ x, uint4* __restrict__ xh) {
    size_t i = (size_t)blockIdx.x * blockDim.x + threadIdx.x;
    float4 a = x[2 * i];
    float4 b = x[2 * i + 1];
    uint4 o;
    o.x = h2pack(a.x, a.y);
    o.y = h2pack(a.z, a.w);
    o.z = h2pack(b.x, b.y);
    o.w = h2pack(b.z, b.w);
    xh[i] = o;
}

// W fp32 [e][k][n] -> half2 k-pair interleaved: Wh2[(e*K/2 + kp)*N + n] = {W[2kp][n], W[2kp+1][n]}
template <int K, int N>
__global__ void k_convw(const float* __restrict__ W, uint32_t* __restrict__ Wh2) {
    size_t i = (size_t)blockIdx.x * blockDim.x + threadIdx.x;  // E*(K/2)*(N/4) threads
    size_t n4 = i % (N / 4);
    size_t ekp = i / (N / 4);
    const float* s = W + ekp * 2 * N + n4 * 4;
    float4 r0 = *(const float4*)s;
    float4 r1 = *(const float4*)(s + N);
    uint4 o;
    o.x = h2pack(r0.x, r1.x);
    o.y = h2pack(r0.y, r1.y);
    o.z = h2pack(r0.z, r1.z);
    o.w = h2pack(r0.w, r1.w);
    *(uint4*)(Wh2 + ekp * N + n4 * 4) = o;
}

// ---------------- fp16 mma.sync grouped GEMM (R12 skeleton) ----------------
// CTA 128x128, K-chunk 32, 4 warps (2m x 2n), warp tile 64x64, 3-stage cp.async.
// A (half) cp.async from g_xh / g_h; B (half2 k-pair interleaved) cp.async from g_w*h.
// MODE 1: g_h[segRow, n] = half(gelu( sum_k xh[perm[row], k] * W1[e,k,n] ))
// MODE 2: out[tok, n]    = w[tok] * sum_k g_h[segRow, k] * W2[e,k,n]
template <int KDIM, int NDIM, int MODE>
__global__ void __launch_bounds__(128, 2) k_gemm(const uint32_t* __restrict__ Bh2,
                                                 float* __restrict__ C) {
    extern __shared__ char sm[];
    const int e = blockIdx.z;
    const int segOff = g_offs[e];
    const int cnt = g_offs[e + 1] - segOff;
    const int rowBase = blockIdx.y * 128;
    if (rowBase >= cnt) return;  // padded grid: empty tiles exit
    const int colBase = blockIdx.x * 128;
    const int tid = threadIdx.x;

    int* toks = (int*)sm;
    float* wts = (float*)(sm + 512);
    {
        int r = rowBase + tid;
        int tk = (r < cnt) ? g_perm[segOff + r] : -1;
        toks[tid] = tk;
        wts[tid] = (tk >= 0) ? g_w[tk] : 0.f;
    }
    __syncthreads();

    const uint32_t sb = smem_u32(sm);

    // A: thread tid owns row tid (64B of halves per chunk = 4 x 16B)
    const __half* Aeff = (MODE == 1) ? g_xh : g_h;
    const __half* aSrc;
    {
        int ar;
        if (MODE == 1) {
            int tk = toks[tid];
            ar = (tk >= 0) ? tk : 0;
        } else {
            ar = segOff + ((rowBase + tid < cnt) ? rowBase + tid : 0);
        }
        aSrc = Aeff + (size_t)ar * KDIM;
    }
    // B: thread -> kpair = tid>>3, 16B pieces at (tid&7)*16 + j*128 within the 512B row
    const uint32_t* bSrc = Bh2 + ((size_t)e * (KDIM / 2) + (tid >> 3)) * NDIM + colBase + (tid & 7) * 4;

    const uint32_t dA = sb + OFF_STG + (uint32_t)tid * (SA4 * 4);
    const uint32_t dB = sb + OFF_STG + ASZ + (uint32_t)(tid >> 3) * (SB4 * 4) + (tid & 7) * 16;

    auto issue = [&](int st, int c) {
        const __half* as = aSrc + (size_t)c * 32;
        uint32_t da = dA + st * STAGE;
#pragma unroll
        for (int j = 0; j < 4; j++) CPA16(da + j * 16, as + j * 8);
        const uint32_t* bs = bSrc + (size_t)c * 16 * NDIM;
        uint32_t db = dB + st * STAGE;
#pragma unroll
        for (int j = 0; j < 4; j++) CPA16(db + j * 128, bs + j * 32);
        CPA_COMMIT();
    };

    // fragments: 4 warps, 2m x 2n, warp 64x64
    const int w = tid >> 5;
    const int lane = tid & 31;
    const int g = lane >> 2;
    const int tg = lane & 3;
    const int wm = (w & 1) * 64;
    const int wn = (w >> 1) * 64;

    float acc[4][8][4];
#pragma unroll
    for (int i = 0; i < 4; i++)
#pragma unroll
        for (int j = 0; j < 8; j++)
#pragma unroll
            for (int q = 0; q < 4; q++) acc[i][j][q] = 0.f;

    const int NC = KDIM / 32;
    issue(0, 0);
    issue(1, 1);

    for (int it = 0; it < NC; ++it) {
        if (it + 1 < NC) { CPA_WAIT1(); } else { CPA_WAIT0(); }
        __syncthreads();
        if (it + 2 < NC) issue((it + 2) % 3, it + 2);

        const uint32_t* As = (const uint32_t*)(sm + OFF_STG + (it % 3) * STAGE);
        const uint32_t* Bs = (const uint32_t*)(sm + OFF_STG + (it % 3) * STAGE + ASZ);

#pragma unroll
        for (int s = 0; s < 2; s++) {
            const int kc = s * 8;  // half2 k-offset
            uint32_t ua[4][4], ub[8][2];
#pragma unroll
            for (int i = 0; i < 4; i++) {
                const int row = wm + i * 16 + g;
                ua[i][0] = As[row * SA4 + kc + tg];
                ua[i][1] = As[(row + 8) * SA4 + kc + tg];
                ua[i][2] = As[row * SA4 + kc + tg + 4];
                ua[i][3] = As[(row + 8) * SA4 + kc + tg + 4];
            }
#pragma unroll
            for (int j = 0; j < 8; j++) {
                const int n = wn + j * 8 + g;
                ub[j][0] = Bs[(kc + tg) * SB4 + n];
                ub[j][1] = Bs[(kc + tg + 4) * SB4 + n];
            }
#pragma unroll
            for (int i = 0; i < 4; i++)
#pragma unroll
                for (int j = 0; j < 8; j++)
                    mma16(acc[i][j][0], acc[i][j][1], acc[i][j][2], acc[i][j][3],
                          ua[i][0], ua[i][1], ua[i][2], ua[i][3], ub[j][0], ub[j][1]);
        }
    }

    // epilogue
#pragma unroll
    for (int i = 0; i < 4; i++) {
#pragma unroll
        for (int h = 0; h < 2; h++) {
            const int rl = wm + i * 16 + g + 8 * h;
            const int rg = rowBase + rl;
            if (rg >= cnt) continue;
            if (MODE == 1) {
                __half* out = g_h + (size_t)(segOff + rg) * NDIM + colBase;
#pragma unroll
                for (int j = 0; j < 8; j++) {
                    const int col = wn + j * 8 + 2 * tg;
                    __half2 v = __floats2half2_rn(gelu_exact(acc[i][j][2 * h]),
                                                  gelu_exact(acc[i][j][2 * h + 1]));
                    *(__half2*)(out + col) = v;
                }
            } else {
                float* out = C + (size_t)toks[rl] * NDIM + colBase;
                const float wv = wts[rl];
#pragma unroll
                for (int j = 0; j < 8; j++) {
                    const int col = wn + j * 8 + 2 * tg;
                    float2 v;
                    v.x = acc[i][j][2 * h] * wv;
                    v.y = acc[i][j][2 * h + 1] * wv;
                    *(float2*)(out + col) = v;
                }
            }
        }
    }
}

extern "C" void kernel_launch(void* const* d_in, const int* in_sizes, int n_in,
                              void* d_out, int out_size) {
    (void)in_sizes;
    (void)n_in;
    (void)out_size;
    const float* x  = (const float*)d_in[0];
    const float* Wr = (const float*)d_in[1];
    const float* W1 = (const float*)d_in[2];
    const float* W2 = (const float*)d_in[3];
    float* out = (float*)d_out;

    cudaFuncSetAttribute(k_gemm<DD, FFDIM, 1>,
                         cudaFuncAttributeMaxDynamicSharedMemorySize, SMEM_SZ);
    cudaFuncSetAttribute(k_gemm<FFDIM, DD, 2>,
                         cudaFuncAttributeMaxDynamicSharedMemorySize, SMEM_SZ);

    __half* xh;
    uint32_t *w1h, *w2h;
    cudaGetSymbolAddress((void**)&xh, g_xh);
    cudaGetSymbolAddress((void**)&w1h, g_w1h);
    cudaGetSymbolAddress((void**)&w2h, g_w2h);

    k_init<<<1, 32>>>();
    k_router<<<TT / 8, 256>>>(x, Wr);
    k_scan<<<1, 32>>>();
    k_scatter<<<TT / 256, 256>>>();

    k_convx<<<(TT * DD / 8) / 256, 256>>>((const float4*)x, (uint4*)xh);
    k_convw<DD, FFDIM><<<(EE * (DD / 2) * (FFDIM / 4)) / 256, 256>>>(W1, w1h);
    k_convw<FFDIM, DD><<<(EE * (FFDIM / 2) * (DD / 4)) / 256, 256>>>(W2, w2h);

    dim3 g1(FFDIM / 128, TT / 128, EE);  // 64 x 32 x 8 (empty padded tiles exit)
    k_gemm<DD, FFDIM, 1><<<g1, 128, SMEM_SZ>>>(w1h, nullptr);

    dim3 g2(DD / 128, TT / 128, EE);     // 16 x 32 x 8
    k_gemm<FFDIM, DD, 2><<<g2, 128, SMEM_SZ>>>(w2h, out);
}